// round 12
// baseline (speedup 1.0000x reference)
#include <cuda_runtime.h>
#include <cstdint>
#include <cstddef>

#define B_   16
#define CI_  32
#define HH   224
#define WW   224
#define CO_  32
#define OH_  222
#define OW_  222

// converted operands: per cell 32 words, fragment-vectorized order:
//   uint4[ch*4 + t] = { hi_{ch*8+t}, hi_{ch*8+t+4}, lo_{ch*8+t}, lo_{ch*8+t+4} }
static __device__ __align__(16) unsigned int g_xcvt[(size_t)B_ * HH * WW * 32];
static __device__ __align__(16) unsigned int g_wcvt[9 * CO_ * 32];

#define THREADS 256
#define TILES   4            // tiles per CTA
#define NTILES  (B_ * 222)   // 3552 logical tiles (2 x-halves * 111 y * 16 b)
#define TROWS 4
#define TCOLS 136
#define SA_PLANE (TROWS * TCOLS * 16)       // 8704 words
#define SB_PLANE (9 * CO_ * 16)             // 4608 words
#define SMEM_WORDS (2 * SA_PLANE + 2 * SB_PLANE)   // 26624
#define SMEM_BYTES (SMEM_WORDS * 4)                // 106496 -> 2 CTAs/SM

__device__ __forceinline__ unsigned pack_hi_trunc(unsigned u0, unsigned u1) {
    unsigned d;
    asm("prmt.b32 %0, %1, %2, 0x7632;" : "=r"(d) : "r"(u0), "r"(u1));
    return d;
}
__device__ __forceinline__ unsigned pack_bf16x2(float even, float odd) {
    unsigned d;
    asm("cvt.rn.bf16x2.f32 %0, %1, %2;" : "=r"(d) : "f"(odd), "f"(even));
    return d;
}
__device__ __forceinline__ void mma_bf16(float* c, unsigned a0, unsigned a1,
                                         unsigned a2, unsigned a3,
                                         unsigned b0, unsigned b1) {
    asm volatile(
        "mma.sync.aligned.m16n8k16.row.col.f32.bf16.bf16.f32 "
        "{%0,%1,%2,%3}, {%4,%5,%6,%7}, {%8,%9}, {%0,%1,%2,%3};"
        : "+f"(c[0]), "+f"(c[1]), "+f"(c[2]), "+f"(c[3])
        : "r"(a0), "r"(a1), "r"(a2), "r"(a3), "r"(b0), "r"(b1));
}
__device__ __forceinline__ void cp16(unsigned dst, const void* src, int nbytes) {
    asm volatile("cp.async.cg.shared.global [%0], [%1], 16, %2;"
                 :: "r"(dst), "l"(src), "r"(nbytes) : "memory");
}
#define CP_COMMIT() asm volatile("cp.async.commit_group;" ::: "memory")
#define CP_WAIT1()  asm volatile("cp.async.wait_group 1;" ::: "memory")
#define CP_WAIT0()  asm volatile("cp.async.wait_group 0;" ::: "memory")

__device__ __forceinline__ void emit_cell(uint4* d4, const unsigned* hw, const unsigned* lw) {
    #pragma unroll
    for (int ch = 0; ch < 2; ++ch)
        #pragma unroll
        for (int t = 0; t < 4; ++t)
            d4[ch * 4 + t] = make_uint4(hw[ch * 8 + t], hw[ch * 8 + t + 4],
                                        lw[ch * 8 + t], lw[ch * 8 + t + 4]);
}

// ---- pre-pass: convert x (and, in the tail block, w) ----
#define XBLOCKS ((B_ * HH * 7 * 32) / 256)     // 3136
__global__ void __launch_bounds__(256) cvt_xw(const float* __restrict__ x,
                                              const float* __restrict__ w) {
    if (blockIdx.x == XBLOCKS) {
        for (int r = threadIdx.x; r < 288; r += 256) {
            const int tap = r >> 5, co = r & 31;
            unsigned hw[16], lw[16];
            #pragma unroll
            for (int p = 0; p < 16; ++p) {
                float v0 = __ldg(&w[co * 288 + (2 * p) * 9 + tap]);
                float v1 = __ldg(&w[co * 288 + (2 * p + 1) * 9 + tap]);
                unsigned u0 = __float_as_uint(v0), u1 = __float_as_uint(v1);
                hw[p] = pack_hi_trunc(u0, u1);
                lw[p] = pack_bf16x2(v0 - __uint_as_float(u0 & 0xffff0000u),
                                    v1 - __uint_as_float(u1 & 0xffff0000u));
            }
            emit_cell((uint4*)(g_wcvt + (size_t)r * 32), hw, lw);
        }
        return;
    }
    const int lane = threadIdx.x & 31;
    const int W    = (blockIdx.x * 256 + threadIdx.x) >> 5;
    const int wb   = W % 7;
    const int h    = (W / 7) % HH;
    const int b    = W / (7 * HH);
    const int iw   = wb * 32 + lane;

    unsigned hw[16], lw[16];
    #pragma unroll
    for (int p = 0; p < 16; ++p) {
        size_t i0 = (((size_t)b * CI_ + 2 * p) * HH + h) * WW + iw;
        float v0 = __ldg(&x[i0]);
        float v1 = __ldg(&x[i0 + (size_t)HH * WW]);
        unsigned u0 = __float_as_uint(v0), u1 = __float_as_uint(v1);
        hw[p] = pack_hi_trunc(u0, u1);
        lw[p] = pack_bf16x2(v0 - __uint_as_float(u0 & 0xffff0000u),
                            v1 - __uint_as_float(u1 & 0xffff0000u));
    }
    emit_cell((uint4*)(g_xcvt + (((size_t)b * HH + h) * WW + iw) * 32), hw, lw);
}

// decode logical tile id -> (b, oh0, px0)
__device__ __forceinline__ void decode_tile(int lin, int& b, int& oh0, int& px0) {
    b = lin / 222;
    int rem = lin - b * 222;
    px0 = (rem & 1) ? 94 : 0;
    oh0 = (rem >> 1) * 2;
}

// issue cp.async for one A plane (ch) of tile (b, oh0, px0) into smem dst
__device__ __forceinline__ void issue_A(unsigned dA, int b, int oh0, int px0,
                                        int ch, int tid) {
    const int so = ch * 16;
    #pragma unroll
    for (int trow = 0; trow < TROWS; ++trow) {
        const unsigned* gr = g_xcvt + (((size_t)b * HH + oh0 + trow) * WW) * 32;
        const unsigned dAr = dA + (unsigned)(trow * TCOLS * 64);
        for (int i = tid; i < TCOLS * 4; i += THREADS) {
            int col = i >> 2, sub = i & 3;
            int iw  = px0 + col;
            int ok  = (iw < WW);
            cp16(dAr + (unsigned)(col * 64 + sub * 16),
                 gr + (size_t)(ok ? iw : 0) * 32 + so + sub * 4, ok ? 16 : 0);
        }
    }
}

// compute all 9 taps for one ci-half plane (216 MMAs per warp)
__device__ __forceinline__ void compute_plane(const unsigned* __restrict__ sA,
                                              const unsigned* __restrict__ sB,
                                              float acc[2][4][4],
                                              int orow, int mq, int g, int t) {
    #pragma unroll
    for (int ky = 0; ky < 3; ++ky) {
        #pragma unroll
        for (int kx = 0; kx < 3; ++kx) {
            const unsigned* bp = sB + (((ky * 3 + kx) * 32) + g) * 16 + t * 4;
            uint4 bf[4];
            #pragma unroll
            for (int nt = 0; nt < 4; ++nt)
                bf[nt] = *(const uint4*)(bp + nt * (8 * 16));

            const unsigned* ap = sA + (((orow + ky) * TCOLS + mq * 32 + kx + g)) * 16 + t * 4;
            #pragma unroll
            for (int mt = 0; mt < 2; ++mt) {
                uint4 aL = *(const uint4*)(ap + mt * (16 * 16));
                uint4 aH = *(const uint4*)(ap + (mt * 16 + 8) * 16);
                #pragma unroll
                for (int nt = 0; nt < 4; ++nt) {
                    mma_bf16(acc[mt][nt], aL.x, aH.x, aL.y, aH.y, bf[nt].x, bf[nt].y);
                    mma_bf16(acc[mt][nt], aL.x, aH.x, aL.y, aH.y, bf[nt].z, bf[nt].w);
                    mma_bf16(acc[mt][nt], aL.z, aH.z, aL.w, aH.w, bf[nt].x, bf[nt].y);
                }
            }
        }
    }
}

// ---- main: 4 tiles per CTA, B loaded once, A plane-stream double-buffered ----
__global__ void __launch_bounds__(THREADS, 2)
conv3x3_mma(const float* __restrict__ bias, float* __restrict__ out) {
    extern __shared__ unsigned smw[];
    unsigned* sA[2] = { smw, smw + SA_PLANE };          // A ch0 / ch1 buffers
    unsigned* sB[2] = { smw + 2 * SA_PLANE, smw + 2 * SA_PLANE + SB_PLANE };
    const unsigned aA[2] = { (unsigned)__cvta_generic_to_shared(sA[0]),
                             (unsigned)__cvta_generic_to_shared(sA[1]) };
    const unsigned aB0   = (unsigned)__cvta_generic_to_shared(sB[0]);

    const int tid = threadIdx.x;
    const int blk = blockIdx.x;
    const int lin0 = blk * TILES;

    int b0, oh00, px00;
    decode_tile(lin0, b0, oh00, px00);

    // ---- G0: B (both planes) + A(tile0, ch0)
    for (int i = tid; i < 288 * 8; i += THREADS) {   // B: row-major, both ch
        int row = i >> 3, sub = i & 7;
        // sub 0-3 -> ch0 plane, 4-7 -> ch1 plane (contiguous SB planes)
        unsigned dst = aB0 + (unsigned)((sub < 4 ? 0 : SB_PLANE * 4)
                                        + row * 64 + (sub & 3) * 16);
        cp16(dst, g_wcvt + (size_t)row * 32 + sub * 4, 16);
    }
    issue_A(aA[0], b0, oh00, px00, 0, tid);
    CP_COMMIT();
    // ---- G1: A(tile0, ch1)
    issue_A(aA[1], b0, oh00, px00, 1, tid);
    CP_COMMIT();

    const int lane = tid & 31;
    const int wid  = tid >> 5;
    const int g = lane >> 2, t = lane & 3;
    const int orow = wid & 1;
    const int mq   = wid >> 1;

    #pragma unroll 1
    for (int tl = 0; tl < TILES; ++tl) {
        int b, oh0, px0;
        decode_tile(lin0 + tl, b, oh0, px0);

        float acc[2][4][4];
        #pragma unroll
        for (int mt = 0; mt < 2; mt++)
            #pragma unroll
            for (int nt = 0; nt < 4; nt++)
                #pragma unroll
                for (int i = 0; i < 4; i++) acc[mt][nt][i] = 0.f;

        #pragma unroll
        for (int ch = 0; ch < 2; ++ch) {
            const int j = 2 * tl + ch;
            if (j >= 2 * TILES - 2) { CP_WAIT0(); } else { CP_WAIT1(); }
            __syncthreads();
            compute_plane(sA[ch], sB[ch], acc, orow, mq, g, t);
            __syncthreads();                 // buffer sA[ch] free for reuse
            if (j + 2 < 2 * TILES) {         // prefetch same-ch plane of next tile
                int bn, ohn, pxn;
                decode_tile(lin0 + tl + 1, bn, ohn, pxn);
                issue_A(aA[ch], bn, ohn, pxn, ch, tid);
                CP_COMMIT();
            }
        }

        // ---- epilogue for this tile (rows always in range: 222 = 2*111)
        const int oy = oh0 + orow;
        #pragma unroll
        for (int nt = 0; nt < 4; ++nt) {
            const int co0 = nt * 8 + t * 2;
            const float bs0 = __ldg(&bias[co0]);
            const float bs1 = __ldg(&bias[co0 + 1]);
            float* o0 = out + (((size_t)b * CO_ + co0)     * OH_ + oy) * OW_;
            float* o1 = out + (((size_t)b * CO_ + co0 + 1) * OH_ + oy) * OW_;
            #pragma unroll
            for (int mt = 0; mt < 2; ++mt) {
                const int pl = px0 + mq * 32 + mt * 16 + g;
                o0[pl]     = acc[mt][nt][0] + bs0;
                o1[pl]     = acc[mt][nt][1] + bs1;
                o0[pl + 8] = acc[mt][nt][2] + bs0;
                o1[pl + 8] = acc[mt][nt][3] + bs1;
            }
        }
    }
}

extern "C" void kernel_launch(void* const* d_in, const int* in_sizes, int n_in,
                              void* d_out, int out_size)
{
    const float* x    = (const float*)d_in[0];
    const float* w    = (const float*)d_in[1];
    const float* bias = (const float*)d_in[2];
    float* out        = (float*)d_out;

    cvt_xw<<<XBLOCKS + 1, 256>>>(x, w);

    cudaFuncSetAttribute(conv3x3_mma,
                         cudaFuncAttributeMaxDynamicSharedMemorySize, SMEM_BYTES);
    conv3x3_mma<<<NTILES / TILES, THREADS, SMEM_BYTES>>>(bias, out);
}